// round 14
// baseline (speedup 1.0000x reference)
#include <cuda_runtime.h>
#include <cuda_fp16.h>
#include <cstdint>

// ============================================================================
// Problem constants
// ============================================================================
#define BATCH   8192
#define FDIM    64
#define NXC     82
#define NYC     67
#define PDIM    5494          // NXC*NYC
#define PPAD    5504          // 43 * 128, zero-padded
#define TILE_N  128
#define MTILE   32            // rows per m-step
#define MSTEPS  4             // m-steps per CTA: CTA covers 128 batch rows
#define PITCH   144           // smem operand row pitch bytes (128B data + 16B pad)
#define OPITCHF 132           // output staging pitch in floats (128 + 4)

// ============================================================================
// Scratch (device globals; no allocation allowed)
// ============================================================================
__device__ __align__(16) __half g_Ah[BATCH * FDIM];   // fp16 inputs
__device__ __align__(16) __half g_Wh[PPAD * FDIM];    // fp16 W, rows permuted
__device__ __align__(16) float  g_bias[PPAD];

// ============================================================================
// Fused prep: fp16 convert + W row permutation (transpose fold) + bias
// ============================================================================
__global__ void prep_kernel(const float* __restrict__ A,
                            const float* __restrict__ W,
                            const float* __restrict__ b) {
    int e = blockIdx.x * blockDim.x + threadIdx.x;
    if (e < BATCH * FDIM) {
        g_Ah[e] = __float2half(A[e]);
    } else {
        int e2 = e - BATCH * FDIM;
        if (e2 < PPAD * FDIM) {
            int q = e2 >> 6, f = e2 & 63;   // q = x*67 + y
            float v = 0.0f;
            if (q < PDIM) {
                int x = q / NYC, y = q % NYC;
                v = W[(y * NXC + x) * FDIM + f];
            }
            g_Wh[e2] = __float2half(v);
            if (f == 0) {
                float bv = 0.0f;
                if (q < PDIM) {
                    int x = q / NYC, y = q % NYC;
                    bv = b[y * NXC + x];
                }
                g_bias[q] = bv;
            }
        }
    }
}

// ============================================================================
// Helpers
// ============================================================================
__device__ __forceinline__ uint32_t smem_u32(const void* p) {
    uint32_t a;
    asm("{ .reg .u64 t; cvta.to.shared.u64 t, %1; cvt.u32.u64 %0, t; }"
        : "=r"(a) : "l"(p));
    return a;
}

__device__ __forceinline__ void cpasync16(uint32_t dst, const void* src) {
    asm volatile("cp.async.cg.shared.global [%0], [%1], 16;"
                 :: "r"(dst), "l"(src));
}
#define CP_COMMIT() asm volatile("cp.async.commit_group;" ::: "memory")
#define CP_WAIT(n)  asm volatile("cp.async.wait_group %0;" :: "n"(n) : "memory")

__device__ __forceinline__ void ldm_x4(uint32_t& r0, uint32_t& r1,
                                       uint32_t& r2, uint32_t& r3, uint32_t addr) {
    asm volatile("ldmatrix.sync.aligned.m8n8.x4.shared.b16 {%0,%1,%2,%3}, [%4];"
                 : "=r"(r0), "=r"(r1), "=r"(r2), "=r"(r3) : "r"(addr));
}

__device__ __forceinline__ void mma16816(float* c, const uint32_t* a,
                                         uint32_t b0, uint32_t b1) {
    asm volatile(
        "mma.sync.aligned.m16n8k16.row.col.f32.f16.f16.f32 "
        "{%0,%1,%2,%3}, {%4,%5,%6,%7}, {%8,%9}, {%0,%1,%2,%3};"
        : "+f"(c[0]), "+f"(c[1]), "+f"(c[2]), "+f"(c[3])
        : "r"(a[0]), "r"(a[1]), "r"(a[2]), "r"(a[3]), "r"(b0), "r"(b1));
}

// ============================================================================
// GEMM: single-pass fp16, 4 CTAs/SM (small tiles, <=64 regs). W fragment set
// (32 regs) loaded ONCE per CTA and reused across all 4 m-steps. Warp tile
// 16x32 (2M x 4N over each 32x128 m-step). Transposed smem epilogue.
// ============================================================================
#define SM_A     0                            // 128*144 = 18432
#define SM_W     18432                        // 128*144 = 18432
#define SM_BIAS  36864                        // 512
#define SM_O     37376                        // 32*132*4 = 16896
#define SMEM_BYTES 54272                      // x4 = 217 KB <= 228 KB

__global__ void __launch_bounds__(256, 4) gemm_kernel(float* __restrict__ out) {
    extern __shared__ char smem[];
    uint32_t sb = smem_u32(smem);
    int tid  = threadIdx.x;
    int lane = tid & 31;
    int wid  = tid >> 5;
    int wm   = wid & 1;        // warp row (0..1) -> 16 rows each
    int wn   = wid >> 1;       // warp col (0..3) -> 32 cols each
    int n0 = blockIdx.x * TILE_N;
    int m0 = blockIdx.y * (MTILE * MSTEPS);   // 128 rows per CTA

    // ---- stage A rows (128x128B) + W tile (128x128B) + bias, once ----
    {
        const char* gA = (const char*)(g_Ah + (size_t)m0 * FDIM);
        const char* gW = (const char*)(g_Wh + (size_t)n0 * FDIM);
        #pragma unroll
        for (int i = tid; i < 128 * 8; i += 256) {
            int r = i >> 3, ch = i & 7;
            cpasync16(sb + SM_A + r * PITCH + ch * 16, gA + r * 128 + ch * 16);
            cpasync16(sb + SM_W + r * PITCH + ch * 16, gW + r * 128 + ch * 16);
        }
        if (tid < TILE_N)
            ((float*)(smem + SM_BIAS))[tid] = g_bias[n0 + tid];
    }
    CP_COMMIT();
    CP_WAIT(0);
    __syncthreads();

    // ---- W fragments -> registers ONCE: [kk][nq][4] = 32 regs ----
    uint32_t bBase = sb + SM_W
        + (uint32_t)(wn * 32 + ((lane >> 4) << 3) + (lane & 7)) * PITCH
        + (((lane >> 3) & 1) * 16);
    uint32_t bF[4][2][4];
    #pragma unroll
    for (int kk = 0; kk < 4; kk++)
        #pragma unroll
        for (int nq = 0; nq < 2; nq++)
            ldm_x4(bF[kk][nq][0], bF[kk][nq][1], bF[kk][nq][2], bF[kk][nq][3],
                   bBase + nq * 16 * PITCH + kk * 32);

    uint32_t aOff = sb + SM_A
        + (uint32_t)(wm * 16 + (lane & 15)) * PITCH + ((lane >> 4) * 16);
    int g = lane >> 2, t = lane & 3;

    // per-lane epilogue constants: lane covers cols {2*lane, 2*lane+1} in each
    // 64-col phase of a row (same for every row)
    const float* sbias = (const float*)(smem + SM_BIAS);
    float2 bias2[2];
    bool pvalid[2];
    #pragma unroll
    for (int ph = 0; ph < 2; ph++) {
        bias2[ph].x = sbias[ph * 64 + 2 * lane];
        bias2[ph].y = sbias[ph * 64 + 2 * lane + 1];
        pvalid[ph] = (n0 + ph * 64 + 2 * lane) < PDIM;  // PDIM even -> pair safe
    }

    uint32_t oBase = sb + SM_O;
    uint32_t stsR = (uint32_t)(wm * 16 + g);          // (+8 for upper half)
    uint32_t stsC = (uint32_t)(wn * 32 + 2 * t);      // + ni*8

    #pragma unroll 1
    for (int mt = 0; mt < MSTEPS; mt++) {
        float c[4][4];
        #pragma unroll
        for (int ni = 0; ni < 4; ni++)
            #pragma unroll
            for (int r = 0; r < 4; r++) c[ni][r] = 0.0f;

        uint32_t aBase = aOff + (uint32_t)(mt * MTILE) * PITCH;
        #pragma unroll
        for (int kk = 0; kk < 4; kk++) {     // K=64: 4 k-steps of 16
            uint32_t aF[4];
            ldm_x4(aF[0], aF[1], aF[2], aF[3], aBase + kk * 32);
            #pragma unroll
            for (int ni = 0; ni < 4; ni++)
                mma16816(c[ni], aF,
                         bF[kk][ni >> 1][(ni & 1) * 2],
                         bF[kk][ni >> 1][(ni & 1) * 2 + 1]);
        }

        // ---- dump accumulators to staging tile (32 x OPITCHF floats) ----
        #pragma unroll
        for (int ni = 0; ni < 4; ni++) {
            uint32_t cadr = oBase + ((stsR * OPITCHF + stsC + ni * 8) << 2);
            asm volatile("st.shared.v2.f32 [%0], {%1, %2};"
                         :: "r"(cadr), "f"(c[ni][0]), "f"(c[ni][1]) : "memory");
            asm volatile("st.shared.v2.f32 [%0], {%1, %2};"
                         :: "r"(cadr + ((8u * OPITCHF) << 2)),
                            "f"(c[ni][2]), "f"(c[ni][3]) : "memory");
        }
        __syncthreads();

        // ---- contiguous row stores: warp wid handles rows wid*4..wid*4+3 ----
        int mrow = m0 + mt * MTILE;
        #pragma unroll
        for (int r = 0; r < 4; r++) {
            int lr = wid * 4 + r;                      // local row 0..31
            float* orow = out + (size_t)(mrow + lr) * PDIM + n0;
            uint32_t radr = oBase + ((uint32_t)(lr * OPITCHF + 2 * lane) << 2);
            #pragma unroll
            for (int ph = 0; ph < 2; ph++) {
                if (pvalid[ph]) {
                    float2 v;
                    asm volatile("ld.shared.v2.f32 {%0, %1}, [%2];"
                                 : "=f"(v.x), "=f"(v.y)
                                 : "r"(radr + ((ph * 64u) << 2)));
                    v.x += bias2[ph].x;
                    v.y += bias2[ph].y;
                    *(float2*)(orow + ph * 64 + 2 * lane) = v;
                }
            }
        }
        if (mt + 1 < MSTEPS) __syncthreads();  // staging reusable next m-step
    }
}

// ============================================================================
// Launch
// ============================================================================
extern "C" void kernel_launch(void* const* d_in, const int* in_sizes, int n_in,
                              void* d_out, int out_size) {
    const float* A = (const float*)d_in[0];   // [8192, 64]
    const float* W = (const float*)d_in[1];   // [5494, 64]
    const float* b = (const float*)d_in[2];   // [5494]
    float* out = (float*)d_out;               // [8192, 82, 67, 1] contiguous

    cudaFuncSetAttribute(gemm_kernel,
                         cudaFuncAttributeMaxDynamicSharedMemorySize, SMEM_BYTES);

    int prep_elems = BATCH * FDIM + PPAD * FDIM;
    prep_kernel<<<(prep_elems + 255) / 256, 256>>>(A, W, b);

    dim3 grid(PPAD / TILE_N, BATCH / (MTILE * MSTEPS));   // 43 x 64
    gemm_kernel<<<grid, 256, SMEM_BYTES>>>(out);
}

// round 16
// speedup vs baseline: 1.5063x; 1.5063x over previous
#include <cuda_runtime.h>
#include <cuda_fp16.h>
#include <cstdint>

// ============================================================================
// Problem constants
// ============================================================================
#define BATCH   8192
#define FDIM    64
#define NXC     82
#define NYC     67
#define PDIM    5494          // NXC*NYC
#define PPAD    5504          // 43 * 128, zero-padded
#define TILE_N  128
#define MTILE   64            // rows per m-step
#define MSTEPS  2             // m-steps per CTA: CTA covers 128 batch rows
#define PITCH   144           // smem operand row pitch bytes (128B data + 16B pad)
#define OPITCHF 36            // per-warp staging pitch in floats (EVEN: v2 8B-aligned)
#define OWARPB  (32 * OPITCHF * 4)   // 4608 B per-warp staging block

// ============================================================================
// Scratch (device globals; no allocation allowed)
// ============================================================================
__device__ __align__(16) __half g_Ah[BATCH * FDIM];   // fp16 inputs
__device__ __align__(16) __half g_Wh[PPAD * FDIM];    // fp16 W, rows permuted
__device__ __align__(16) float  g_bias[PPAD];

// ============================================================================
// Fused prep: fp16 convert + W row permutation (transpose fold) + bias
// ============================================================================
__global__ void prep_kernel(const float* __restrict__ A,
                            const float* __restrict__ W,
                            const float* __restrict__ b) {
    int e = blockIdx.x * blockDim.x + threadIdx.x;
    if (e < BATCH * FDIM) {
        g_Ah[e] = __float2half(A[e]);
    } else {
        int e2 = e - BATCH * FDIM;
        if (e2 < PPAD * FDIM) {
            int q = e2 >> 6, f = e2 & 63;   // q = x*67 + y
            float v = 0.0f;
            if (q < PDIM) {
                int x = q / NYC, y = q % NYC;
                v = W[(y * NXC + x) * FDIM + f];
            }
            g_Wh[e2] = __float2half(v);
            if (f == 0) {
                float bv = 0.0f;
                if (q < PDIM) {
                    int x = q / NYC, y = q % NYC;
                    bv = b[y * NXC + x];
                }
                g_bias[q] = bv;
            }
        }
    }
}

// ============================================================================
// Helpers
// ============================================================================
__device__ __forceinline__ uint32_t smem_u32(const void* p) {
    uint32_t a;
    asm("{ .reg .u64 t; cvta.to.shared.u64 t, %1; cvt.u32.u64 %0, t; }"
        : "=r"(a) : "l"(p));
    return a;
}

__device__ __forceinline__ void cpasync16(uint32_t dst, const void* src) {
    asm volatile("cp.async.cg.shared.global [%0], [%1], 16;"
                 :: "r"(dst), "l"(src));
}
#define CP_COMMIT() asm volatile("cp.async.commit_group;" ::: "memory")
#define CP_WAIT(n)  asm volatile("cp.async.wait_group %0;" :: "n"(n) : "memory")

__device__ __forceinline__ void ldm_x4(uint32_t& r0, uint32_t& r1,
                                       uint32_t& r2, uint32_t& r3, uint32_t addr) {
    asm volatile("ldmatrix.sync.aligned.m8n8.x4.shared.b16 {%0,%1,%2,%3}, [%4];"
                 : "=r"(r0), "=r"(r1), "=r"(r2), "=r"(r3) : "r"(addr));
}

__device__ __forceinline__ void mma16816(float* c, const uint32_t* a,
                                         uint32_t b0, uint32_t b1) {
    asm volatile(
        "mma.sync.aligned.m16n8k16.row.col.f32.f16.f16.f32 "
        "{%0,%1,%2,%3}, {%4,%5,%6,%7}, {%8,%9}, {%0,%1,%2,%3};"
        : "+f"(c[0]), "+f"(c[1]), "+f"(c[2]), "+f"(c[3])
        : "r"(a[0]), "r"(a[1]), "r"(a[2]), "r"(a[3]), "r"(b0), "r"(b1));
}

// ============================================================================
// GEMM: single-pass fp16, 3 CTAs/SM, warp 32x32 mainloop (bF in halves),
// PER-WARP transposed epilogue: each warp transposes its own 32x32 block in a
// private staging area (EVEN pitch -> v2 aligned) -> only __syncwarp()
// between STS and LDS; ZERO CTA-wide barriers after the staging sync.
// ============================================================================
#define SM_A     0                            // 128*144 = 18432
#define SM_W     18432                        // 128*144 = 18432
#define SM_BIAS  36864                        // 512
#define SM_O     37376                        // 8 * 4608 = 36864
#define SMEM_BYTES 74240                      // x3 = 222.7 KB <= 228 KB

__global__ void __launch_bounds__(256, 3) gemm_kernel(float* __restrict__ out) {
    extern __shared__ char smem[];
    uint32_t sb = smem_u32(smem);
    int tid  = threadIdx.x;
    int lane = tid & 31;
    int wid  = tid >> 5;
    int wm   = wid & 1;        // warp row (0..1) -> 32 rows each
    int wn   = wid >> 1;       // warp col (0..3) -> 32 cols each
    int n0 = blockIdx.x * TILE_N;
    int m0 = blockIdx.y * (MTILE * MSTEPS);   // 128 rows per CTA

    // ---- stage A rows (128x128B) + W tile (128x128B) + bias, once ----
    {
        const char* gA = (const char*)(g_Ah + (size_t)m0 * FDIM);
        const char* gW = (const char*)(g_Wh + (size_t)n0 * FDIM);
        #pragma unroll
        for (int i = tid; i < 128 * 8; i += 256) {
            int r = i >> 3, ch = i & 7;
            cpasync16(sb + SM_A + r * PITCH + ch * 16, gA + r * 128 + ch * 16);
            cpasync16(sb + SM_W + r * PITCH + ch * 16, gW + r * 128 + ch * 16);
        }
        if (tid < TILE_N)
            ((float*)(smem + SM_BIAS))[tid] = g_bias[n0 + tid];
    }
    CP_COMMIT();
    CP_WAIT(0);
    __syncthreads();            // the ONLY CTA-wide barrier

    uint32_t bBase = sb + SM_W
        + (uint32_t)(wn * 32 + ((lane >> 4) << 3) + (lane & 7)) * PITCH
        + (((lane >> 3) & 1) * 16);
    uint32_t aOff = sb + SM_A
        + (uint32_t)(wm * 32 + (lane & 15)) * PITCH + ((lane >> 4) * 16);
    int g = lane >> 2, t = lane & 3;

    // ---- per-lane epilogue constants ----
    // Store phase: lane handles cols wn*32 + (lane&15)*2 (+1), rows 2r+(lane>>4)
    int colL = (lane & 15) * 2;
    int ncol = n0 + wn * 32 + colL;
    const float* sbias = (const float*)(smem + SM_BIAS);
    float2 bias2;
    bias2.x = sbias[wn * 32 + colL];
    bias2.y = sbias[wn * 32 + colL + 1];
    bool pval = ncol < PDIM;                  // PDIM even -> pair safe

    uint32_t wBase = sb + SM_O + (uint32_t)wid * OWARPB;  // private staging
    // STS address (within warp's 32x32 block): row g (+8/+16/+24), col 2t (+ni*8)
    uint32_t stsBase = wBase + (uint32_t)((g * OPITCHF + 2 * t) << 2);
    // LDS address: row = 2r + (lane>>4), col = colL
    uint32_t ldsBase = wBase + (uint32_t)(((lane >> 4) * OPITCHF + colL) << 2);

    #pragma unroll 1
    for (int mt = 0; mt < MSTEPS; mt++) {
        float c[2][4][4];
        #pragma unroll
        for (int mi = 0; mi < 2; mi++)
            #pragma unroll
            for (int ni = 0; ni < 4; ni++)
                #pragma unroll
                for (int r = 0; r < 4; r++) c[mi][ni][r] = 0.0f;

        uint32_t aBase = aOff + (uint32_t)(mt * MTILE) * PITCH;

        // ---- k-loop in two halves; only half the W frags live at a time ----
        #pragma unroll
        for (int kh = 0; kh < 2; kh++) {
            uint32_t bF[2][2][4];          // [kk in half][nq][4] = 16 regs
            #pragma unroll
            for (int kk = 0; kk < 2; kk++)
                #pragma unroll
                for (int nq = 0; nq < 2; nq++)
                    ldm_x4(bF[kk][nq][0], bF[kk][nq][1],
                           bF[kk][nq][2], bF[kk][nq][3],
                           bBase + nq * 16 * PITCH + (kh * 2 + kk) * 32);
            #pragma unroll
            for (int kk = 0; kk < 2; kk++) {
                uint32_t aF[2][4];
                #pragma unroll
                for (int mi = 0; mi < 2; mi++)
                    ldm_x4(aF[mi][0], aF[mi][1], aF[mi][2], aF[mi][3],
                           aBase + mi * 16 * PITCH + (kh * 2 + kk) * 32);
                #pragma unroll
                for (int mi = 0; mi < 2; mi++)
                    #pragma unroll
                    for (int ni = 0; ni < 4; ni++)
                        mma16816(c[mi][ni], aF[mi],
                                 bF[kk][ni >> 1][(ni & 1) * 2],
                                 bF[kk][ni >> 1][(ni & 1) * 2 + 1]);
            }
        }

        // ---- per-warp transpose: STS own 32x32 block (pitch 36 floats) ----
        #pragma unroll
        for (int mi = 0; mi < 2; mi++)
            #pragma unroll
            for (int ni = 0; ni < 4; ni++) {
                uint32_t cadr = stsBase
                    + (uint32_t)(((mi * 16) * OPITCHF + ni * 8) << 2);
                asm volatile("st.shared.v2.f32 [%0], {%1, %2};"
                             :: "r"(cadr), "f"(c[mi][ni][0]), "f"(c[mi][ni][1])
                             : "memory");
                asm volatile("st.shared.v2.f32 [%0], {%1, %2};"
                             :: "r"(cadr + ((8u * OPITCHF) << 2)),
                                "f"(c[mi][ni][2]), "f"(c[mi][ni][3])
                             : "memory");
            }
        __syncwarp();

        // ---- contiguous stores: 2 rows per iter, 16 LDS+STG pairs ----
        if (pval) {
            int mrow = m0 + mt * MTILE + wm * 32;
            #pragma unroll
            for (int r = 0; r < 16; r++) {
                int row = 2 * r + (lane >> 4);         // 0..31
                float2 v;
                asm volatile("ld.shared.v2.f32 {%0, %1}, [%2];"
                             : "=f"(v.x), "=f"(v.y)
                             : "r"(ldsBase + ((uint32_t)(2 * r * OPITCHF) << 2)));
                v.x += bias2.x;
                v.y += bias2.y;
                *(float2*)(out + (size_t)(mrow + row) * PDIM + ncol) = v;
            }
        }
        __syncwarp();   // own staging reusable next m-step (warp-local)
    }
}

// ============================================================================
// Launch
// ============================================================================
extern "C" void kernel_launch(void* const* d_in, const int* in_sizes, int n_in,
                              void* d_out, int out_size) {
    const float* A = (const float*)d_in[0];   // [8192, 64]
    const float* W = (const float*)d_in[1];   // [5494, 64]
    const float* b = (const float*)d_in[2];   // [5494]
    float* out = (float*)d_out;               // [8192, 82, 67, 1] contiguous

    cudaFuncSetAttribute(gemm_kernel,
                         cudaFuncAttributeMaxDynamicSharedMemorySize, SMEM_BYTES);

    int prep_elems = BATCH * FDIM + PPAD * FDIM;
    prep_kernel<<<(prep_elems + 255) / 256, 256>>>(A, W, b);

    dim3 grid(PPAD / TILE_N, BATCH / (MTILE * MSTEPS));   // 43 x 64
    gemm_kernel<<<grid, 256, SMEM_BYTES>>>(out);
}